// round 3
// baseline (speedup 1.0000x reference)
#include <cuda_runtime.h>
#include <cuda_fp16.h>
#include <cstdint>

// ---------------------------------------------------------------------------
// TensoRF NeRF renderer, HMMA v2.
//  - persistent CTAs (1/SM), 512 threads, all weights fp16 in smem
//  - 4x4 warp grid, 32x32 tiles: A & B each read 4x (was 2x/8x) -> less LDSM
//  - IN double-buffered 64-col chunks; gmem loads for chunk c+1 issued BEFORE
//    MMA of chunk c (latency hidden), sincos+STS after
//  - layer3 (128->3) + sigmoid done from layer-2 registers, no 3rd GEMM
// ---------------------------------------------------------------------------

#define S         128
#define NTHREADS  512

#define STRIDE_W1 136     // halves; 272B rows (16B-aligned, conflict-free)
#define STRIDE_W2 136
#define STRIDE_H  136
#define STRIDE_IN 72      // 64-col chunk + 8 pad; 144B rows

// smem offsets (bytes)
#define OFF_W1    0
#define OFF_W2    (OFF_W1 + 400*STRIDE_W1*2)     // 108800
#define OFF_H     (OFF_W2 + 128*STRIDE_W2*2)     // 143616
#define OFF_IN0   (OFF_H  + 128*STRIDE_H*2)      // 178432
#define OFF_IN1   (OFF_IN0 + 128*STRIDE_IN*2)    // 196864
#define OFF_W3    (OFF_IN1 + 128*STRIDE_IN*2)    // 215296  f32 [128][3]
#define OFF_WGT   (OFF_W3 + 1536)                // 216832
#define OFF_RGB   (OFF_WGT + 512)                // 217344  f32 [128][3]
#define OFF_B1    (OFF_RGB + 1536)               // 218880
#define OFF_B2    (OFF_B1 + 512)                 // 219392
#define OFF_B3    (OFF_B2 + 512)                 // 219904
#define OFF_ACC   (OFF_B3 + 16)                  // 219920
#define SMEM_BYTES (OFF_ACC + 16)                // 219936 (<= 232448)

// ---------------------------------------------------------------------------
__device__ __forceinline__ uint32_t smem_u32(const void* p) {
    return (uint32_t)__cvta_generic_to_shared(p);
}
__device__ __forceinline__ void ldmA4(uint32_t a[4], uint32_t addr) {
    asm volatile("ldmatrix.sync.aligned.m8n8.x4.shared.b16 {%0,%1,%2,%3}, [%4];"
                 : "=r"(a[0]), "=r"(a[1]), "=r"(a[2]), "=r"(a[3]) : "r"(addr));
}
__device__ __forceinline__ void ldmBT4(uint32_t b[4], uint32_t addr) {
    asm volatile("ldmatrix.sync.aligned.m8n8.x4.trans.shared.b16 {%0,%1,%2,%3}, [%4];"
                 : "=r"(b[0]), "=r"(b[1]), "=r"(b[2]), "=r"(b[3]) : "r"(addr));
}
__device__ __forceinline__ void mma16816(float c[4], const uint32_t a[4],
                                         uint32_t b0, uint32_t b1) {
    asm volatile("mma.sync.aligned.m16n8k16.row.col.f32.f16.f16.f32 "
                 "{%0,%1,%2,%3}, {%4,%5,%6,%7}, {%8,%9}, {%0,%1,%2,%3};"
                 : "+f"(c[0]), "+f"(c[1]), "+f"(c[2]), "+f"(c[3])
                 : "r"(a[0]), "r"(a[1]), "r"(a[2]), "r"(a[3]), "r"(b0), "r"(b1));
}
__device__ __forceinline__ uint32_t packh2(float a, float b) {
    __half2 h = __floats2half2_rn(a, b);
    return *(uint32_t*)&h;
}
__device__ __forceinline__ float sigmoidf_(float x) {
    return 1.0f / (1.0f + __expf(-x));
}

// K permutation: k in [0,360): channel cc=k/12, f=(k%12)/2, odd=cos of x*2^f
//                k in [360,387): raw app;  [387,390): raw view;  [390,400): 0
__device__ __forceinline__ int orig_row(int k) {
    if (k < 360) {
        int cc = k / 12;
        int f  = (k % 12) >> 1;
        int isc = k & 1;
        if (cc < 27) return 30 + cc*6 + f + (isc ? 162 : 0);
        return 354 + (cc - 27)*6 + f + (isc ? 18 : 0);
    }
    if (k < 387) return k - 360;
    if (k < 390) return 27 + (k - 387);
    return -1;
}

// ---- chunked fill: chunk c covers k in [64c, 64c+64) (c<6) or [384,400) ----
// pair-channel range for chunk c<6: ccLo=(16c)/3, ccHi=min(29,(64c+63)/12)
__device__ __forceinline__ void fill_load(int c, int tid,
                                          const float* __restrict__ gApp,
                                          const float* __restrict__ gView,
                                          float pv[2], float rv[3][2]) {
    if (c < 6) {
        int ccLo = (16*c)/3;
        int ccHi = min(29, (64*c + 63)/12);
        int nch  = ccHi - ccLo + 1;
        #pragma unroll
        for (int t = 0; t < 2; t++) {
            int i = tid + NTHREADS*t;
            if (i < 128*nch) {
                int s = i / nch, cc = ccLo + (i - s*nch);
                pv[t] = (cc < 27) ? gApp[s*27 + cc] : gView[s*3 + (cc - 27)];
            }
        }
        if (c == 5) {
            #pragma unroll
            for (int t = 0; t < 3; t++) {        // 128*12 pair-items: raw app 0..23
                int i = tid + NTHREADS*t;
                int s = i / 12, j2 = (i - s*12)*2;
                rv[t][0] = gApp[s*27 + j2];
                rv[t][1] = gApp[s*27 + j2 + 1];
            }
        }
    } else {                                      // c==6: k 384..399
        #pragma unroll
        for (int t = 0; t < 2; t++) {             // 128*8 u32 items
            int i = tid + NTHREADS*t;
            int s = i >> 3, p = i & 7;
            int c0 = 24 + 2*p, c1 = c0 + 1;
            rv[t][0] = (c0 < 27) ? gApp[s*27 + c0]
                     : ((c0 < 30) ? gView[s*3 + c0 - 27] : 0.0f);
            rv[t][1] = (c1 < 27) ? gApp[s*27 + c1]
                     : ((c1 < 30) ? gView[s*3 + c1 - 27] : 0.0f);
        }
    }
}

__device__ __forceinline__ void fill_store(int c, int tid, __half* buf,
                                           const float pv[2], float rv[3][2]) {
    const int k0 = 64*c;
    if (c < 6) {
        int ccLo = (16*c)/3;
        int ccHi = min(29, (64*c + 63)/12);
        int nch  = ccHi - ccLo + 1;
        #pragma unroll
        for (int t = 0; t < 2; t++) {
            int i = tid + NTHREADS*t;
            if (i < 128*nch) {
                int s = i / nch, cc = ccLo + (i - s*nch);
                float sn, cs;
                __sincosf(pv[t], &sn, &cs);
                #pragma unroll
                for (int f = 0; f < 6; f++) {
                    int k = 12*cc + 2*f;
                    if ((unsigned)(k - k0) < 64u)
                        *(uint32_t*)&buf[s*STRIDE_IN + (k - k0)] = packh2(sn, cs);
                    float s2 = 2.0f*sn*cs, c2 = 1.0f - 2.0f*sn*sn;
                    sn = s2; cs = c2;
                }
            }
        }
        if (c == 5) {
            #pragma unroll
            for (int t = 0; t < 3; t++) {
                int i = tid + NTHREADS*t;
                int s = i / 12, j2 = (i - s*12)*2;
                *(uint32_t*)&buf[s*STRIDE_IN + 40 + j2] = packh2(rv[t][0], rv[t][1]);
            }
        }
    } else {
        #pragma unroll
        for (int t = 0; t < 2; t++) {
            int i = tid + NTHREADS*t;
            int s = i >> 3, p = i & 7;
            *(uint32_t*)&buf[s*STRIDE_IN + 2*p] = packh2(rv[t][0], rv[t][1]);
        }
    }
}

// ---- one K-chunk of MMA: A[32 x len] (strideA) @ B[len x 32] (W, stride 136)
__device__ __forceinline__ void mma_block(float acc[2][4][4],
                                          uint32_t aBase, int strideA,
                                          uint32_t wBase, int wrow0, int len,
                                          int mq, int nq, int lr, int lc8) {
    #pragma unroll 4
    for (int kk = 0; kk < len; kk += 16) {
        uint32_t a0[4], a1[4], b0[4], b1[4];
        ldmA4(a0, aBase + (uint32_t)(((32*mq + lr)*strideA + kk + lc8) * 2));
        ldmA4(a1, aBase + (uint32_t)(((32*mq + 16 + lr)*strideA + kk + lc8) * 2));
        ldmBT4(b0, wBase + (uint32_t)(((wrow0 + kk + lr)*STRIDE_W1 + 32*nq + lc8) * 2));
        ldmBT4(b1, wBase + (uint32_t)(((wrow0 + kk + lr)*STRIDE_W1 + 32*nq + 16 + lc8) * 2));
        mma16816(acc[0][0], a0, b0[0], b0[1]);
        mma16816(acc[0][1], a0, b0[2], b0[3]);
        mma16816(acc[0][2], a0, b1[0], b1[1]);
        mma16816(acc[0][3], a0, b1[2], b1[3]);
        mma16816(acc[1][0], a1, b0[0], b0[1]);
        mma16816(acc[1][1], a1, b0[2], b0[3]);
        mma16816(acc[1][2], a1, b1[0], b1[1]);
        mma16816(acc[1][3], a1, b1[2], b1[3]);
    }
}

// ---------------------------------------------------------------------------

__global__ void __launch_bounds__(NTHREADS, 1)
nerf_render_kernel(const float* __restrict__ sigma_feat,
                   const float* __restrict__ app,
                   const float* __restrict__ view,
                   const float* __restrict__ dists,
                   const float* __restrict__ W1, const float* __restrict__ b1,
                   const float* __restrict__ W2, const float* __restrict__ b2,
                   const float* __restrict__ W3, const float* __restrict__ b3,
                   float* __restrict__ out, int R)
{
    extern __shared__ char sm[];
    __half* sW1 = (__half*)(sm + OFF_W1);
    __half* sW2 = (__half*)(sm + OFF_W2);
    __half* sH  = (__half*)(sm + OFF_H);
    __half* sIn[2] = { (__half*)(sm + OFF_IN0), (__half*)(sm + OFF_IN1) };
    float* sW3  = (float*)(sm + OFF_W3);
    float* sWgt = (float*)(sm + OFF_WGT);
    float* sRGB = (float*)(sm + OFF_RGB);
    float* sB1  = (float*)(sm + OFF_B1);
    float* sB2  = (float*)(sm + OFF_B2);
    float* sB3  = (float*)(sm + OFF_B3);
    float* sAcc = (float*)(sm + OFF_ACC);

    const int tid  = threadIdx.x;
    const int lane = tid & 31;
    const int warp = tid >> 5;
    const int mq   = warp & 3;          // row group (32 rows)
    const int nq   = warp >> 2;         // col group (32 cols)
    const int lr   = lane & 15;
    const int lc8  = (lane >> 4) << 3;
    const int rr   = lane >> 2;         // 0..7
    const int cb   = (lane & 3) << 1;   // 0,2,4,6

    // ---- one-time: weights -> smem fp16 (W1 K-permuted) ----
    for (int idx = tid; idx < 400*128; idx += NTHREADS) {
        int k = idx >> 7, n = idx & 127;
        int o = orig_row(k);
        float v = (o >= 0) ? W1[o*128 + n] : 0.0f;
        sW1[k*STRIDE_W1 + n] = __float2half(v);
    }
    for (int idx = tid; idx < 128*128; idx += NTHREADS) {
        int k = idx >> 7, n = idx & 127;
        sW2[k*STRIDE_W2 + n] = __float2half(W2[idx]);
    }
    for (int i = tid; i < 128*3; i += NTHREADS) sW3[i] = W3[i];
    if (tid < 128) { sB1[tid] = b1[tid]; sB2[tid] = b2[tid]; }
    if (tid < 3)   sB3[tid] = b3[tid];

    const uint32_t w1Base = smem_u32(sW1);
    const uint32_t w2Base = smem_u32(sW2);
    const uint32_t hBase  = smem_u32(sH);
    const uint32_t inBase[2] = { smem_u32(sIn[0]), smem_u32(sIn[1]) };

    for (int ray = blockIdx.x; ray < R; ray += gridDim.x) {
        __syncthreads();   // smem reuse + out-write of previous ray complete

        const float* gApp  = app  + (size_t)ray * (S*27);
        const float* gView = view + (size_t)ray * (S*3);

        // reset accumulation buffers
        for (int i = tid; i < 384; i += NTHREADS) sRGB[i] = 0.0f;
        if (tid < 4) sAcc[tid] = 0.0f;

        // warp 15: alpha + segmented compositing scan -> sWgt (overlaps fill 0)
        if (warp == 15) {
            float a[4], t[4];
            #pragma unroll
            for (int j = 0; j < 4; j++) {
                int s2 = 4*lane + j;
                float x  = sigma_feat[(size_t)ray*S + s2] - 10.0f;
                float sp = (x > 20.0f) ? x : log1pf(__expf(x));
                float av = 1.0f - __expf(-sp * dists[(size_t)ray*S + s2] * 25.0f);
                if (s2 == S-1) av = 1.0f;
                a[j] = av; t[j] = 1.0f - av + 1e-10f;
            }
            float incl = t[0]*t[1]*t[2]*t[3];
            #pragma unroll
            for (int off = 1; off < 32; off <<= 1) {
                float v = __shfl_up_sync(0xffffffffu, incl, off);
                if (lane >= off) incl *= v;
            }
            float T = __shfl_up_sync(0xffffffffu, incl, 1);
            if (lane == 0) T = 1.0f;
            #pragma unroll
            for (int j = 0; j < 4; j++) { sWgt[4*lane + j] = a[j]*T; T *= t[j]; }
        }

        // ---- fill chunk 0 ----
        {
            float pv[2]; float rv[3][2];
            fill_load(0, tid, gApp, gView, pv, rv);
            fill_store(0, tid, sIn[0], pv, rv);
        }
        __syncthreads();

        // ---- layer 1: pipelined chunks ----
        float acc[2][4][4];
        #pragma unroll
        for (int i = 0; i < 2; i++)
            #pragma unroll
            for (int j = 0; j < 4; j++)
                #pragma unroll
                for (int q = 0; q < 4; q++) acc[i][j][q] = 0.0f;

        #pragma unroll 1
        for (int c = 0; c < 7; c++) {
            float pv[2]; float rv[3][2];
            if (c < 6) fill_load(c + 1, tid, gApp, gView, pv, rv);  // LDG first
            mma_block(acc, inBase[c & 1], STRIDE_IN, w1Base, 64*c,
                      (c == 6) ? 16 : 64, mq, nq, lr, lc8);
            if (c < 6) fill_store(c + 1, tid, sIn[(c + 1) & 1], pv, rv);
            __syncthreads();
        }

        // ---- epilogue 1: bias + relu -> H fp16 ----
        #pragma unroll
        for (int t = 0; t < 2; t++) {
            int r = 32*mq + 16*t + rr;
            #pragma unroll
            for (int u = 0; u < 4; u++) {
                int cc = 32*nq + 8*u + cb;
                float bb0 = sB1[cc], bb1 = sB1[cc+1];
                *(uint32_t*)&sH[r*STRIDE_H + cc] =
                    packh2(fmaxf(acc[t][u][0] + bb0, 0.0f),
                           fmaxf(acc[t][u][1] + bb1, 0.0f));
                *(uint32_t*)&sH[(r+8)*STRIDE_H + cc] =
                    packh2(fmaxf(acc[t][u][2] + bb0, 0.0f),
                           fmaxf(acc[t][u][3] + bb1, 0.0f));
            }
        }
        __syncthreads();

        // ---- layer 2 ----
        #pragma unroll
        for (int i = 0; i < 2; i++)
            #pragma unroll
            for (int j = 0; j < 4; j++)
                #pragma unroll
                for (int q = 0; q < 4; q++) acc[i][j][q] = 0.0f;

        mma_block(acc, hBase, STRIDE_H, w2Base, 0, 128, mq, nq, lr, lc8);

        // ---- epilogue 2: bias+relu in reg, layer3 dot, quad-reduce, atomics ----
        {
            float p[2][2][3];
            #pragma unroll
            for (int t = 0; t < 2; t++)
                #pragma unroll
                for (int v = 0; v < 2; v++)
                    #pragma unroll
                    for (int o = 0; o < 3; o++) p[t][v][o] = 0.0f;

            #pragma unroll
            for (int t = 0; t < 2; t++) {
                #pragma unroll
                for (int u = 0; u < 4; u++) {
                    int cc = 32*nq + 8*u + cb;
                    float bb0 = sB2[cc], bb1 = sB2[cc+1];
                    float h00 = fmaxf(acc[t][u][0] + bb0, 0.0f);
                    float h01 = fmaxf(acc[t][u][1] + bb1, 0.0f);
                    float h10 = fmaxf(acc[t][u][2] + bb0, 0.0f);
                    float h11 = fmaxf(acc[t][u][3] + bb1, 0.0f);
                    #pragma unroll
                    for (int o = 0; o < 3; o++) {
                        p[t][0][o] += h00*sW3[cc*3 + o] + h01*sW3[(cc+1)*3 + o];
                        p[t][1][o] += h10*sW3[cc*3 + o] + h11*sW3[(cc+1)*3 + o];
                    }
                }
            }
            #pragma unroll
            for (int t = 0; t < 2; t++)
                #pragma unroll
                for (int v = 0; v < 2; v++)
                    #pragma unroll
                    for (int o = 0; o < 3; o++) {
                        float x = p[t][v][o];
                        x += __shfl_xor_sync(0xffffffffu, x, 1);
                        x += __shfl_xor_sync(0xffffffffu, x, 2);
                        p[t][v][o] = x;
                    }
            if ((lane & 3) == 0) {
                #pragma unroll
                for (int t = 0; t < 2; t++)
                    #pragma unroll
                    for (int v = 0; v < 2; v++) {
                        int r = 32*mq + 16*t + 8*v + rr;
                        #pragma unroll
                        for (int o = 0; o < 3; o++)
                            atomicAdd(&sRGB[r*3 + o], p[t][v][o]);
                    }
            }
        }
        __syncthreads();

        // ---- sigmoid + composite weights + reduce over samples ----
        if (tid < 384) {
            int c  = tid >> 7;
            int s2 = tid & 127;
            float v = sWgt[s2] * sigmoidf_(sRGB[s2*3 + c] + sB3[c]);
            #pragma unroll
            for (int off = 16; off; off >>= 1)
                v += __shfl_down_sync(0xffffffffu, v, off);
            if (lane == 0) atomicAdd(&sAcc[c], v);
        }
        __syncthreads();
        if (tid < 3) out[(size_t)ray*3 + tid] = sAcc[tid];
    }
}

// ---------------------------------------------------------------------------

extern "C" void kernel_launch(void* const* d_in, const int* in_sizes, int n_in,
                              void* d_out, int out_size) {
    const float* sigma_feat = (const float*)d_in[0];
    const float* app        = (const float*)d_in[1];
    const float* viewd      = (const float*)d_in[2];
    const float* dists      = (const float*)d_in[3];
    const float* W1         = (const float*)d_in[4];
    const float* b1         = (const float*)d_in[5];
    const float* W2         = (const float*)d_in[6];
    const float* b2         = (const float*)d_in[7];
    const float* W3         = (const float*)d_in[8];
    const float* b3         = (const float*)d_in[9];
    float* out = (float*)d_out;

    int R = in_sizes[0] / S;   // 4096

    int sms = 0;
    cudaDeviceGetAttribute(&sms, cudaDevAttrMultiProcessorCount, 0);
    if (sms <= 0) sms = 148;
    int grid = sms < R ? sms : R;

    cudaFuncSetAttribute(nerf_render_kernel,
                         cudaFuncAttributeMaxDynamicSharedMemorySize, SMEM_BYTES);

    nerf_render_kernel<<<grid, NTHREADS, SMEM_BYTES>>>(
        sigma_feat, app, viewd, dists, W1, b1, W2, b2, W3, b3, out, R);
}